// round 1
// baseline (speedup 1.0000x reference)
#include <cuda_runtime.h>
#include <cuda_bf16.h>

// Problem constants
#define OBS 128
#define NAGENT 16
#define HID 128
#define GE 256
#define LE 256
#define F1 512
#define F2 512
#define NACT 8
#define MAXB 2048
#define MAXM (MAXB * NAGENT)

// Scratch (device globals -- no allocation allowed)
__device__ float g_x[MAXM * HID];       // relu(obs@W_pre+b)
__device__ float g_loc[MAXM * LE];      // relu(obs@W_loc+b)
__device__ float g_xbar[MAXB * HID];    // mean over agents of x
__device__ float g_s0[MAXB * HID];
__device__ float g_s1[MAXB * HID];
__device__ float g_g[MAXB * GE];
__device__ float g_G1[MAXB * F1];       // g@W1_top + b1 (per-sample addend)
__device__ float g_z1[MAXM * F1];
__device__ float g_z2[MAXM * F2];

// ---------------------------------------------------------------------------
// Tiled fp32 GEMM: C[M,N] = epilogue(A[M,K] @ B[K,N])
//   epilogue: + bias[n] (opt) + rowAdd[(m/16)*N + n] (opt), relu (opt)
// BM=BN=64, BK=16, 256 threads, 4x4 outputs/thread.
// Requires M%64==0, N%64==0, K%16==0 (true for all call sites).
// ---------------------------------------------------------------------------
__global__ __launch_bounds__(256) void sgemm64(
    const float* __restrict__ A, const float* __restrict__ B,
    float* __restrict__ C, int M, int N, int K,
    const float* __restrict__ bias, const float* __restrict__ rowAdd,
    int doRelu)
{
    const int BM = 64, BN = 64, BK = 16;
    __shared__ float As[BK][BM];
    __shared__ float Bs[BK][BN];

    const int tid  = threadIdx.x;
    const int brow = blockIdx.y * BM;
    const int bcol = blockIdx.x * BN;

    // A tile load: BM x BK, one float4 per thread along K
    const int aRow = tid >> 2;          // 0..63
    const int aCol = (tid & 3) * 4;     // 0,4,8,12
    // B tile load: BK x BN, one float4 per thread along N
    const int bRow = tid >> 4;          // 0..15
    const int bCol = (tid & 15) * 4;    // 0..60

    const int tr = tid >> 4;            // 0..15 (row group)
    const int tc = tid & 15;            // 0..15 (col group)

    float acc[4][4] = {};

    for (int k0 = 0; k0 < K; k0 += BK) {
        float4 av = *(const float4*)&A[(long)(brow + aRow) * K + k0 + aCol];
        As[aCol + 0][aRow] = av.x;
        As[aCol + 1][aRow] = av.y;
        As[aCol + 2][aRow] = av.z;
        As[aCol + 3][aRow] = av.w;
        float4 bv = *(const float4*)&B[(long)(k0 + bRow) * N + bcol + bCol];
        *(float4*)&Bs[bRow][bCol] = bv;
        __syncthreads();

#pragma unroll
        for (int k = 0; k < BK; k++) {
            float4 ar = *(const float4*)&As[k][tr * 4];
            float4 br = *(const float4*)&Bs[k][tc * 4];
            float a0 = ar.x, a1 = ar.y, a2 = ar.z, a3 = ar.w;
            float b0 = br.x, b1v = br.y, b2v = br.z, b3v = br.w;
            acc[0][0] = fmaf(a0, b0,  acc[0][0]); acc[0][1] = fmaf(a0, b1v, acc[0][1]);
            acc[0][2] = fmaf(a0, b2v, acc[0][2]); acc[0][3] = fmaf(a0, b3v, acc[0][3]);
            acc[1][0] = fmaf(a1, b0,  acc[1][0]); acc[1][1] = fmaf(a1, b1v, acc[1][1]);
            acc[1][2] = fmaf(a1, b2v, acc[1][2]); acc[1][3] = fmaf(a1, b3v, acc[1][3]);
            acc[2][0] = fmaf(a2, b0,  acc[2][0]); acc[2][1] = fmaf(a2, b1v, acc[2][1]);
            acc[2][2] = fmaf(a2, b2v, acc[2][2]); acc[2][3] = fmaf(a2, b3v, acc[2][3]);
            acc[3][0] = fmaf(a3, b0,  acc[3][0]); acc[3][1] = fmaf(a3, b1v, acc[3][1]);
            acc[3][2] = fmaf(a3, b2v, acc[3][2]); acc[3][3] = fmaf(a3, b3v, acc[3][3]);
        }
        __syncthreads();
    }

#pragma unroll
    for (int i = 0; i < 4; i++) {
        const int row = brow + tr * 4 + i;
        const int col = bcol + tc * 4;
        float4 v;
        v.x = acc[i][0]; v.y = acc[i][1]; v.z = acc[i][2]; v.w = acc[i][3];
        if (bias) {
            v.x += bias[col + 0]; v.y += bias[col + 1];
            v.z += bias[col + 2]; v.w += bias[col + 3];
        }
        if (rowAdd) {
            const float* ra = rowAdd + (long)(row >> 4) * N + col;
            v.x += ra[0]; v.y += ra[1]; v.z += ra[2]; v.w += ra[3];
        }
        if (doRelu) {
            v.x = fmaxf(v.x, 0.f); v.y = fmaxf(v.y, 0.f);
            v.z = fmaxf(v.z, 0.f); v.w = fmaxf(v.w, 0.f);
        }
        *(float4*)&C[(long)row * N + col] = v;
    }
}

// ---------------------------------------------------------------------------
// Mean over 16 agents: xbar[s,c] = mean_a x[s*16+a, c]   (HID=128)
// ---------------------------------------------------------------------------
__global__ void mean16_kernel(const float* __restrict__ x,
                              float* __restrict__ xbar, int S)
{
    int idx = blockIdx.x * blockDim.x + threadIdx.x;
    if (idx >= S * HID) return;
    int s = idx / HID, c = idx % HID;
    const float* p = x + (long)s * NAGENT * HID + c;
    float acc = 0.f;
#pragma unroll
    for (int a = 0; a < NAGENT; a++) acc += p[a * HID];
    xbar[idx] = acc * (1.0f / NAGENT);
}

// ---------------------------------------------------------------------------
// Thin output GEMM: q[M,8] = z2[M,512] @ W3[512,8] + b3. Warp per row.
// ---------------------------------------------------------------------------
__global__ __launch_bounds__(256) void qgemm_kernel(
    const float* __restrict__ z2, const float* __restrict__ W3,
    const float* __restrict__ b3, float* __restrict__ q, int M)
{
    __shared__ float W3s[F2 * NACT];   // 16 KB
    for (int i = threadIdx.x; i < F2 * NACT; i += blockDim.x) W3s[i] = W3[i];
    __syncthreads();

    int warp = threadIdx.x >> 5;
    int lane = threadIdx.x & 31;
    int row  = blockIdx.x * (blockDim.x >> 5) + warp;
    if (row >= M) return;

    const float* zr = z2 + (long)row * F2;
    float acc[NACT] = {};
    for (int k = lane; k < F2; k += 32) {
        float zv = zr[k];
        const float* w = &W3s[k * NACT];
#pragma unroll
        for (int n = 0; n < NACT; n++) acc[n] = fmaf(zv, w[n], acc[n]);
    }
#pragma unroll
    for (int n = 0; n < NACT; n++) {
#pragma unroll
        for (int off = 16; off > 0; off >>= 1)
            acc[n] += __shfl_xor_sync(0xffffffff, acc[n], off);
    }
    if (lane == 0) {
        float* qr = q + (long)row * NACT;
#pragma unroll
        for (int n = 0; n < NACT; n++) qr[n] = acc[n] + b3[n];
    }
}

// ---------------------------------------------------------------------------
extern "C" void kernel_launch(void* const* d_in, const int* in_sizes, int n_in,
                              void* d_out, int out_size)
{
    const float* obs    = (const float*)d_in[0];
    const float* W_pre  = (const float*)d_in[1];
    const float* b_pre  = (const float*)d_in[2];
    const float* W_gcn  = (const float*)d_in[3];   // [2,128,128]
    const float* b_gcn  = (const float*)d_in[4];   // [2,128]
    const float* W_post = (const float*)d_in[5];
    const float* b_post = (const float*)d_in[6];
    const float* W_loc  = (const float*)d_in[7];
    const float* b_loc  = (const float*)d_in[8];
    const float* W1     = (const float*)d_in[9];   // [512,512]
    const float* b1     = (const float*)d_in[10];
    const float* W2     = (const float*)d_in[11];
    const float* b2     = (const float*)d_in[12];
    const float* W3     = (const float*)d_in[13];
    const float* b3     = (const float*)d_in[14];
    float* q = (float*)d_out;

    const int Bsz = in_sizes[0] / (NAGENT * OBS);  // 2048
    const int M   = Bsz * NAGENT;                  // 32768

    float *x, *loc, *xbar, *s0, *s1, *g, *G1, *z1, *z2;
    cudaGetSymbolAddress((void**)&x,    g_x);
    cudaGetSymbolAddress((void**)&loc,  g_loc);
    cudaGetSymbolAddress((void**)&xbar, g_xbar);
    cudaGetSymbolAddress((void**)&s0,   g_s0);
    cudaGetSymbolAddress((void**)&s1,   g_s1);
    cudaGetSymbolAddress((void**)&g,    g_g);
    cudaGetSymbolAddress((void**)&G1,   g_G1);
    cudaGetSymbolAddress((void**)&z1,   g_z1);
    cudaGetSymbolAddress((void**)&z2,   g_z2);

    // 1) x = relu(obs @ W_pre + b_pre)            [M,128]
    sgemm64<<<dim3(HID / 64, M / 64), 256>>>(obs, W_pre, x, M, HID, OBS,
                                             b_pre, nullptr, 1);
    // 2) loc = relu(obs @ W_loc + b_loc)          [M,256]
    sgemm64<<<dim3(LE / 64, M / 64), 256>>>(obs, W_loc, loc, M, LE, OBS,
                                            b_loc, nullptr, 1);
    // 3) xbar = mean over agents of x             [B,128]
    mean16_kernel<<<(Bsz * HID + 255) / 256, 256>>>(x, xbar, Bsz);
    // 4) GCN collapsed per-sample chain
    sgemm64<<<dim3(HID / 64, Bsz / 64), 256>>>(xbar, W_gcn, s0, Bsz, HID, HID,
                                               b_gcn, nullptr, 1);
    sgemm64<<<dim3(HID / 64, Bsz / 64), 256>>>(s0, W_gcn + HID * HID, s1,
                                               Bsz, HID, HID, b_gcn + HID,
                                               nullptr, 1);
    sgemm64<<<dim3(GE / 64, Bsz / 64), 256>>>(s1, W_post, g, Bsz, GE, HID,
                                              b_post, nullptr, 1);
    // 5) G1 = g @ W1[:256,:] + b1                 [B,512] (no relu)
    sgemm64<<<dim3(F1 / 64, Bsz / 64), 256>>>(g, W1, G1, Bsz, F1, GE,
                                              b1, nullptr, 0);
    // 6) z1 = relu(loc @ W1[256:,:] + G1[sample]) [M,512]
    sgemm64<<<dim3(F1 / 64, M / 64), 256>>>(loc, W1 + (long)GE * F1, z1,
                                            M, F1, LE, nullptr, G1, 1);
    // 7) z2 = relu(z1 @ W2 + b2)                  [M,512]
    sgemm64<<<dim3(F2 / 64, M / 64), 256>>>(z1, W2, z2, M, F2, F1,
                                            b2, nullptr, 1);
    // 8) q = z2 @ W3 + b3                         [M,8]
    qgemm_kernel<<<M / 8, 256>>>(z2, W3, b3, q, M);
}

// round 2
// speedup vs baseline: 3.2936x; 3.2936x over previous
#include <cuda_runtime.h>
#include <cuda_fp16.h>
#include <cstdint>

#define OBS 128
#define NAGENT 16
#define HID 128
#define GE 256
#define LE 256
#define F1 512
#define F2 512
#define NACT 8
#define MAXB 2048
#define MAXM (MAXB * NAGENT)

// fp16 weight buffer offsets (in halves)
#define OFF_WPRE  0
#define OFF_WGCN  16384
#define OFF_WPOST 49152
#define OFF_WLOC  81920
#define OFF_W1    114688
#define OFF_W2    376832
#define WH_TOTAL  638976

// Scratch (device globals — no allocation allowed)
__device__ __align__(16) __half g_wh[WH_TOTAL];
__device__ __align__(16) __half g_obs_h[MAXM * OBS];
__device__ __align__(16) __half g_x[MAXM * HID];
__device__ __align__(16) __half g_loc[MAXM * LE];
__device__ __align__(16) __half g_xbar[MAXB * HID];
__device__ __align__(16) __half g_s0[MAXB * HID];
__device__ __align__(16) __half g_s1[MAXB * HID];
__device__ __align__(16) __half g_gv[MAXB * GE];
__device__ __align__(16) float  g_G1[MAXB * F1];
__device__ __align__(16) __half g_z1[MAXM * F1];
__device__ __align__(16) __half g_z2[MAXM * F2];

// ---------------------------------------------------------------------------
// fp16 tensor-core GEMM: C[M,N] = epi(A[M,K] @ B[K,N])
// A,B fp16 row-major. epi: +bias[n] (fp32), +rowAdd[(m>>4)*N+n] (fp32), relu.
// Output: fp16 (Ch) or fp32 (Cf). BM=128, BN=64, BK=32, 256 thr, 8 warps.
// Requires M%128==0, N%64==0, K%32==0.
// ---------------------------------------------------------------------------
#define BM 128
#define BN 64
#define BK 32

__global__ __launch_bounds__(256) void hgemm(
    const __half* __restrict__ A, const __half* __restrict__ B,
    __half* __restrict__ Ch, float* __restrict__ Cf,
    int M, int N, int K,
    const float* __restrict__ bias, const float* __restrict__ rowAdd,
    int doRelu)
{
    __shared__ __half As[2][BM][BK + 8];
    __shared__ __half Bs[2][BK][BN + 8];

    const int tid  = threadIdx.x;
    const int lane = tid & 31;
    const int wid  = tid >> 5;
    const int wm   = wid & 3;    // warp row (32 rows each)
    const int wn   = wid >> 2;   // warp col (32 cols each)
    const int brow = blockIdx.y * BM;
    const int bcol = blockIdx.x * BN;

    // global staging indices
    const int arow = tid >> 2;            // 0..63 (and +64)
    const int ac8  = (tid & 3) * 8;       // half offset within 32
    const int brw  = tid >> 3;            // 0..31
    const int bc8  = (tid & 7) * 8;

    const __half* Ag  = A + (size_t)(brow + arow) * K + ac8;
    const __half* Ag2 = A + (size_t)(brow + arow + 64) * K + ac8;
    const __half* Bg  = B + (size_t)brw * N + bcol + bc8;

    // ldmatrix per-lane coordinates
    const int aRow = wm * 32 + (lane & 15);
    const int aCol = (lane >> 4) * 8;
    const int bRow = (lane & 7) + ((lane >> 3) & 1) * 8;
    const int bCol = wn * 32 + (lane >> 4) * 8;

    float c[2][4][4];
#pragma unroll
    for (int i = 0; i < 2; i++)
#pragma unroll
        for (int j = 0; j < 4; j++)
#pragma unroll
            for (int e = 0; e < 4; e++) c[i][j][e] = 0.f;

    const int nT = K / BK;

    // preload tile 0
    {
        uint4 a0 = *(const uint4*)Ag;
        uint4 a1 = *(const uint4*)Ag2;
        uint4 b0 = *(const uint4*)Bg;
        *(uint4*)&As[0][arow][ac8]      = a0;
        *(uint4*)&As[0][arow + 64][ac8] = a1;
        *(uint4*)&Bs[0][brw][bc8]       = b0;
    }
    __syncthreads();

    for (int t = 0; t < nT; t++) {
        uint4 ra0, ra1, rb;
        if (t + 1 < nT) {
            const int k0 = (t + 1) * BK;
            ra0 = *(const uint4*)(Ag  + k0);
            ra1 = *(const uint4*)(Ag2 + k0);
            rb  = *(const uint4*)(Bg + (size_t)k0 * N);
        }
        const int cur = t & 1;
#pragma unroll
        for (int ks = 0; ks < 2; ks++) {
            uint32_t a[2][4], b[2][4];
#pragma unroll
            for (int mi = 0; mi < 2; mi++) {
                uint32_t addr = (uint32_t)__cvta_generic_to_shared(
                    &As[cur][aRow + mi * 16][ks * 16 + aCol]);
                asm volatile(
                    "ldmatrix.sync.aligned.m8n8.x4.shared.b16 {%0,%1,%2,%3}, [%4];"
                    : "=r"(a[mi][0]), "=r"(a[mi][1]), "=r"(a[mi][2]), "=r"(a[mi][3])
                    : "r"(addr));
            }
#pragma unroll
            for (int pi = 0; pi < 2; pi++) {
                uint32_t addr = (uint32_t)__cvta_generic_to_shared(
                    &Bs[cur][ks * 16 + bRow][bCol + pi * 16]);
                asm volatile(
                    "ldmatrix.sync.aligned.m8n8.x4.trans.shared.b16 {%0,%1,%2,%3}, [%4];"
                    : "=r"(b[pi][0]), "=r"(b[pi][1]), "=r"(b[pi][2]), "=r"(b[pi][3])
                    : "r"(addr));
            }
#pragma unroll
            for (int mi = 0; mi < 2; mi++)
#pragma unroll
                for (int ni = 0; ni < 4; ni++) {
                    uint32_t b0 = b[ni >> 1][(ni & 1) * 2];
                    uint32_t b1 = b[ni >> 1][(ni & 1) * 2 + 1];
                    asm volatile(
                        "mma.sync.aligned.m16n8k16.row.col.f32.f16.f16.f32 "
                        "{%0,%1,%2,%3}, {%4,%5,%6,%7}, {%8,%9}, {%0,%1,%2,%3};"
                        : "+f"(c[mi][ni][0]), "+f"(c[mi][ni][1]),
                          "+f"(c[mi][ni][2]), "+f"(c[mi][ni][3])
                        : "r"(a[mi][0]), "r"(a[mi][1]), "r"(a[mi][2]), "r"(a[mi][3]),
                          "r"(b0), "r"(b1));
                }
        }
        if (t + 1 < nT) {
            const int nxt = cur ^ 1;
            *(uint4*)&As[nxt][arow][ac8]      = ra0;
            *(uint4*)&As[nxt][arow + 64][ac8] = ra1;
            *(uint4*)&Bs[nxt][brw][bc8]       = rb;
            __syncthreads();
        }
    }

    // epilogue
#pragma unroll
    for (int mi = 0; mi < 2; mi++) {
        const int row  = brow + wm * 32 + mi * 16 + (lane >> 2);
        const int row2 = row + 8;
        const float* ra = rowAdd ? rowAdd + (size_t)(row >> 4) * N : nullptr;
#pragma unroll
        for (int ni = 0; ni < 4; ni++) {
            const int col = bcol + wn * 32 + ni * 8 + (lane & 3) * 2;
            float v0 = c[mi][ni][0], v1 = c[mi][ni][1];
            float v2 = c[mi][ni][2], v3 = c[mi][ni][3];
            if (bias) {
                const float bb0 = bias[col], bb1 = bias[col + 1];
                v0 += bb0; v1 += bb1; v2 += bb0; v3 += bb1;
            }
            if (ra) {
                const float r0 = ra[col], r1 = ra[col + 1];
                v0 += r0; v1 += r1; v2 += r0; v3 += r1;
            }
            if (doRelu) {
                v0 = fmaxf(v0, 0.f); v1 = fmaxf(v1, 0.f);
                v2 = fmaxf(v2, 0.f); v3 = fmaxf(v3, 0.f);
            }
            if (Ch) {
                *(__half2*)&Ch[(size_t)row  * N + col] = __floats2half2_rn(v0, v1);
                *(__half2*)&Ch[(size_t)row2 * N + col] = __floats2half2_rn(v2, v3);
            } else {
                *(float2*)&Cf[(size_t)row  * N + col] = make_float2(v0, v1);
                *(float2*)&Cf[(size_t)row2 * N + col] = make_float2(v2, v3);
            }
        }
    }
}

// ---------------------------------------------------------------------------
// Weight conversion fp32 -> fp16 (one launch)
// ---------------------------------------------------------------------------
__global__ void convW(const float* __restrict__ Wpre, const float* __restrict__ Wgcn,
                      const float* __restrict__ Wpost, const float* __restrict__ Wloc,
                      const float* __restrict__ W1, const float* __restrict__ W2,
                      __half* __restrict__ out)
{
    int idx = blockIdx.x * blockDim.x + threadIdx.x;
    if (idx >= WH_TOTAL) return;
    float v;
    if      (idx < OFF_WGCN)  v = Wpre[idx - OFF_WPRE];
    else if (idx < OFF_WPOST) v = Wgcn[idx - OFF_WGCN];
    else if (idx < OFF_WLOC)  v = Wpost[idx - OFF_WPOST];
    else if (idx < OFF_W1)    v = Wloc[idx - OFF_WLOC];
    else if (idx < OFF_W2)    v = W1[idx - OFF_W1];
    else                      v = W2[idx - OFF_W2];
    out[idx] = __float2half_rn(v);
}

// obs fp32 -> fp16 (vectorized x4)
__global__ void convObs(const float4* __restrict__ in, __half2* __restrict__ out, int n4)
{
    int i = blockIdx.x * blockDim.x + threadIdx.x;
    if (i >= n4) return;
    float4 v = in[i];
    out[2 * i]     = __floats2half2_rn(v.x, v.y);
    out[2 * i + 1] = __floats2half2_rn(v.z, v.w);
}

// ---------------------------------------------------------------------------
// Mean over 16 agents (fp16 in/out, fp32 accumulate), HID=128 -> 64 half2/row
// ---------------------------------------------------------------------------
__global__ void mean16h(const __half2* __restrict__ x, __half2* __restrict__ xbar, int S)
{
    int idx = blockIdx.x * blockDim.x + threadIdx.x;
    if (idx >= S * 64) return;
    int s = idx >> 6, c = idx & 63;
    const __half2* p = x + (size_t)s * NAGENT * 64 + c;
    float ax = 0.f, ay = 0.f;
#pragma unroll
    for (int a = 0; a < NAGENT; a++) {
        float2 v = __half22float2(p[a * 64]);
        ax += v.x; ay += v.y;
    }
    xbar[idx] = __floats2half2_rn(ax * (1.f / NAGENT), ay * (1.f / NAGENT));
}

// ---------------------------------------------------------------------------
// Thin output GEMM: q[M,8] = z2[M,512](fp16) @ W3[512,8](fp32) + b3. Warp/row.
// ---------------------------------------------------------------------------
__global__ __launch_bounds__(256) void qgemm(
    const __half* __restrict__ z2, const float* __restrict__ W3,
    const float* __restrict__ b3, float* __restrict__ q, int M)
{
    __shared__ float W3s[F2 * NACT];
    for (int i = threadIdx.x; i < F2 * NACT; i += 256) W3s[i] = W3[i];
    __syncthreads();

    const int warp = threadIdx.x >> 5;
    const int lane = threadIdx.x & 31;
    const int row  = blockIdx.x * 8 + warp;
    if (row >= M) return;

    const __half2* zr = (const __half2*)(z2 + (size_t)row * F2);
    float acc[NACT] = {};
    for (int k2 = lane; k2 < F2 / 2; k2 += 32) {
        float2 z = __half22float2(zr[k2]);
        const float* w0 = &W3s[(2 * k2) * NACT];
#pragma unroll
        for (int n = 0; n < NACT; n++)
            acc[n] = fmaf(z.x, w0[n], fmaf(z.y, w0[NACT + n], acc[n]));
    }
#pragma unroll
    for (int n = 0; n < NACT; n++) {
#pragma unroll
        for (int off = 16; off > 0; off >>= 1)
            acc[n] += __shfl_xor_sync(0xffffffff, acc[n], off);
    }
    if (lane == 0) {
        float* qr = q + (size_t)row * NACT;
#pragma unroll
        for (int n = 0; n < NACT; n++) qr[n] = acc[n] + b3[n];
    }
}

// ---------------------------------------------------------------------------
extern "C" void kernel_launch(void* const* d_in, const int* in_sizes, int n_in,
                              void* d_out, int out_size)
{
    const float* obs    = (const float*)d_in[0];
    const float* W_pre  = (const float*)d_in[1];
    const float* b_pre  = (const float*)d_in[2];
    const float* W_gcn  = (const float*)d_in[3];
    const float* b_gcn  = (const float*)d_in[4];
    const float* W_post = (const float*)d_in[5];
    const float* b_post = (const float*)d_in[6];
    const float* W_loc  = (const float*)d_in[7];
    const float* b_loc  = (const float*)d_in[8];
    const float* W1     = (const float*)d_in[9];
    const float* b1     = (const float*)d_in[10];
    const float* W2     = (const float*)d_in[11];
    const float* b2     = (const float*)d_in[12];
    const float* W3     = (const float*)d_in[13];
    const float* b3     = (const float*)d_in[14];
    float* q = (float*)d_out;

    const int Bsz = in_sizes[0] / (NAGENT * OBS);   // 2048
    const int M   = Bsz * NAGENT;                   // 32768

    __half *wh, *obs_h, *x, *loc, *xbar, *s0, *s1, *gv, *z1, *z2;
    float* G1;
    cudaGetSymbolAddress((void**)&wh,    g_wh);
    cudaGetSymbolAddress((void**)&obs_h, g_obs_h);
    cudaGetSymbolAddress((void**)&x,     g_x);
    cudaGetSymbolAddress((void**)&loc,   g_loc);
    cudaGetSymbolAddress((void**)&xbar,  g_xbar);
    cudaGetSymbolAddress((void**)&s0,    g_s0);
    cudaGetSymbolAddress((void**)&s1,    g_s1);
    cudaGetSymbolAddress((void**)&gv,    g_gv);
    cudaGetSymbolAddress((void**)&G1,    g_G1);
    cudaGetSymbolAddress((void**)&z1,    g_z1);
    cudaGetSymbolAddress((void**)&z2,    g_z2);

    // 0) conversions
    convW<<<(WH_TOTAL + 255) / 256, 256>>>(W_pre, W_gcn, W_post, W_loc, W1, W2, wh);
    convObs<<<(M * OBS / 4 + 255) / 256, 256>>>((const float4*)obs, (__half2*)obs_h,
                                                M * OBS / 4);

    // 1) x = relu(obs @ W_pre + b_pre)                  [M,128]
    hgemm<<<dim3(HID / BN, M / BM), 256>>>(obs_h, wh + OFF_WPRE, x, nullptr,
                                           M, HID, OBS, b_pre, nullptr, 1);
    // 2) loc = relu(obs @ W_loc + b_loc)                [M,256]
    hgemm<<<dim3(LE / BN, M / BM), 256>>>(obs_h, wh + OFF_WLOC, loc, nullptr,
                                          M, LE, OBS, b_loc, nullptr, 1);
    // 3) xbar = mean over agents                        [B,128]
    mean16h<<<(Bsz * 64 + 255) / 256, 256>>>((const __half2*)x, (__half2*)xbar, Bsz);
    // 4) collapsed GCN chain (per-sample rows)
    hgemm<<<dim3(HID / BN, Bsz / BM), 256>>>(xbar, wh + OFF_WGCN, s0, nullptr,
                                             Bsz, HID, HID, b_gcn, nullptr, 1);
    hgemm<<<dim3(HID / BN, Bsz / BM), 256>>>(s0, wh + OFF_WGCN + HID * HID, s1, nullptr,
                                             Bsz, HID, HID, b_gcn + HID, nullptr, 1);
    hgemm<<<dim3(GE / BN, Bsz / BM), 256>>>(s1, wh + OFF_WPOST, gv, nullptr,
                                            Bsz, GE, HID, b_post, nullptr, 1);
    // 5) G1 = g @ W1[:256,:] + b1 (fp32 out, no relu)   [B,512]
    hgemm<<<dim3(F1 / BN, Bsz / BM), 256>>>(gv, wh + OFF_W1, nullptr, G1,
                                            Bsz, F1, GE, b1, nullptr, 0);
    // 6) z1 = relu(loc @ W1[256:,:] + G1[sample])       [M,512]
    hgemm<<<dim3(F1 / BN, M / BM), 256>>>(loc, wh + OFF_W1 + GE * F1, z1, nullptr,
                                          M, F1, LE, nullptr, G1, 1);
    // 7) z2 = relu(z1 @ W2 + b2)                        [M,512]
    hgemm<<<dim3(F2 / BN, M / BM), 256>>>(z1, wh + OFF_W2, z2, nullptr,
                                          M, F2, F1, b2, nullptr, 1);
    // 8) q = z2 @ W3 + b3                               [M,8]
    qgemm<<<M / 8, 256>>>(z2, W3, b3, q, M);
}

// round 3
// speedup vs baseline: 3.7927x; 1.1515x over previous
#include <cuda_runtime.h>
#include <cuda_fp16.h>
#include <cstdint>

#define OBS 128
#define NAGENT 16
#define HID 128
#define GE 256
#define LE 256
#define F1 512
#define F2 512
#define NACT 8
#define MAXB 2048
#define MAXM (MAXB * NAGENT)

// fp16 weight pack offsets (halves)
#define OFF_WCAT  0            // [128, 384] = [W_pre | W_loc]
#define OFF_WGCN  49152        // [2,128,128]
#define OFF_WPOST 81920        // [128,256]
#define OFF_W1    114688       // [512,512]
#define OFF_W2    376832       // [512,512]
#define WH_TOTAL  638976

__device__ __align__(16) __half g_wh[WH_TOTAL];
__device__ __align__(16) float  g_bcat[384];
__device__ __align__(16) __half g_xloc[MAXM * 384];   // [x | loc]
__device__ __align__(16) __half g_xbar[MAXB * HID];
__device__ __align__(16) __half g_s0[MAXB * HID];
__device__ __align__(16) __half g_s1[MAXB * HID];
__device__ __align__(16) __half g_gv[MAXB * GE];
__device__ __align__(16) float  g_G1[MAXB * F1];
__device__ __align__(16) __half g_z1[MAXM * F1];
__device__ __align__(16) __half g_z2[MAXM * F2];

#define BM 128
#define BN 128
#define BK 32

__device__ __forceinline__ void cp16(uint32_t dst, const void* src) {
    asm volatile("cp.async.cg.shared.global [%0], [%1], 16;\n" ::"r"(dst), "l"(src));
}
__device__ __forceinline__ uint32_t smem_u32(const void* p) {
    return (uint32_t)__cvta_generic_to_shared(p);
}

// ---------------------------------------------------------------------------
// fp16 HMMA GEMM: C[M,N] = epi(A[M,K] @ B[K,N]); A row stride lda.
// AF32: A is fp32 (converted on the fly). B fp16 row-major (stride N).
// epi: +bias[n], +rowAdd[(m>>4)*N+n], relu. Out fp16 (Ch) or fp32 (Cf).
// BM=BN=128, BK=32, 256 thr, 8 warps @ 64x32. M%128==0, N%128==0, K%32==0.
// ---------------------------------------------------------------------------
template <int AF32>
__global__ __launch_bounds__(256, 2) void hgemm(
    const void* __restrict__ Ap, const __half* __restrict__ B,
    __half* __restrict__ Ch, float* __restrict__ Cf,
    int M, int N, int K, int lda,
    const float* __restrict__ bias, const float* __restrict__ rowAdd,
    int doRelu)
{
    __shared__ __half As[2][BM][BK + 8];
    __shared__ __half Bs[2][BK][BN + 8];

    const int tid  = threadIdx.x;
    const int lane = tid & 31;
    const int wid  = tid >> 5;
    const int wm   = wid >> 2;     // 0..1  (64-row slab)
    const int wn   = wid & 3;      // 0..3  (32-col slab)
    const int brow = blockIdx.y * BM;
    const int bcol = blockIdx.x * BN;

    const __half* Ah = (const __half*)Ap;
    const float*  Af = (const float*)Ap;

    // A-tile chunks: 128x32 halves = 512 x (8 halves); 2 chunks/thread
    const int ar0 = tid >> 2,          ac0 = (tid & 3) * 8;      // chunk tid
    const int ar1 = (tid + 256) >> 2,  ac1 = ((tid + 256) & 3) * 8;
    // B-tile chunks: 32x128 halves = 512 x (8 halves); 2 chunks/thread
    const int br0 = tid >> 4,          bc0 = (tid & 15) * 8;
    const int br1 = (tid + 256) >> 4,  bc1 = ((tid + 256) & 15) * 8;

    float c[4][4][4];
#pragma unroll
    for (int i = 0; i < 4; i++)
#pragma unroll
        for (int j = 0; j < 4; j++)
#pragma unroll
            for (int e = 0; e < 4; e++) c[i][j][e] = 0.f;

    const int nT = K / BK;

    auto loadStage = [&](int t, int st) {
        const int k0 = t * BK;
        if (AF32) {
#pragma unroll
            for (int j = 0; j < 2; j++) {
                const int r = j ? ar1 : ar0, cc = j ? ac1 : ac0;
                const float4* s =
                    (const float4*)(Af + (size_t)(brow + r) * lda + k0 + cc);
                float4 v0 = s[0], v1 = s[1];
                __half2 h0 = __floats2half2_rn(v0.x, v0.y);
                __half2 h1 = __floats2half2_rn(v0.z, v0.w);
                __half2 h2 = __floats2half2_rn(v1.x, v1.y);
                __half2 h3 = __floats2half2_rn(v1.z, v1.w);
                uint4 u;
                u.x = *(uint32_t*)&h0; u.y = *(uint32_t*)&h1;
                u.z = *(uint32_t*)&h2; u.w = *(uint32_t*)&h3;
                *(uint4*)&As[st][r][cc] = u;
            }
        } else {
            cp16(smem_u32(&As[st][ar0][ac0]),
                 Ah + (size_t)(brow + ar0) * lda + k0 + ac0);
            cp16(smem_u32(&As[st][ar1][ac1]),
                 Ah + (size_t)(brow + ar1) * lda + k0 + ac1);
        }
        cp16(smem_u32(&Bs[st][br0][bc0]), B + (size_t)(k0 + br0) * N + bcol + bc0);
        cp16(smem_u32(&Bs[st][br1][bc1]), B + (size_t)(k0 + br1) * N + bcol + bc1);
    };

    loadStage(0, 0);
    asm volatile("cp.async.commit_group;\n");

    for (int t = 0; t < nT; t++) {
        if (t + 1 < nT) loadStage(t + 1, (t + 1) & 1);
        asm volatile("cp.async.commit_group;\n");
        asm volatile("cp.async.wait_group 1;\n");
        __syncthreads();

        const int st = t & 1;
#pragma unroll
        for (int ks = 0; ks < 2; ks++) {
            uint32_t a[4][4], b[2][4];
#pragma unroll
            for (int mi = 0; mi < 4; mi++) {
                uint32_t addr = smem_u32(
                    &As[st][wm * 64 + mi * 16 + (lane & 15)][ks * 16 + (lane >> 4) * 8]);
                asm volatile(
                    "ldmatrix.sync.aligned.m8n8.x4.shared.b16 {%0,%1,%2,%3}, [%4];"
                    : "=r"(a[mi][0]), "=r"(a[mi][1]), "=r"(a[mi][2]), "=r"(a[mi][3])
                    : "r"(addr));
            }
#pragma unroll
            for (int pi = 0; pi < 2; pi++) {
                uint32_t addr = smem_u32(
                    &Bs[st][ks * 16 + (lane & 7) + ((lane >> 3) & 1) * 8]
                       [wn * 32 + pi * 16 + (lane >> 4) * 8]);
                asm volatile(
                    "ldmatrix.sync.aligned.m8n8.x4.trans.shared.b16 {%0,%1,%2,%3}, [%4];"
                    : "=r"(b[pi][0]), "=r"(b[pi][1]), "=r"(b[pi][2]), "=r"(b[pi][3])
                    : "r"(addr));
            }
#pragma unroll
            for (int mi = 0; mi < 4; mi++)
#pragma unroll
                for (int ni = 0; ni < 4; ni++) {
                    uint32_t b0 = b[ni >> 1][(ni & 1) * 2];
                    uint32_t b1 = b[ni >> 1][(ni & 1) * 2 + 1];
                    asm volatile(
                        "mma.sync.aligned.m16n8k16.row.col.f32.f16.f16.f32 "
                        "{%0,%1,%2,%3}, {%4,%5,%6,%7}, {%8,%9}, {%0,%1,%2,%3};"
                        : "+f"(c[mi][ni][0]), "+f"(c[mi][ni][1]),
                          "+f"(c[mi][ni][2]), "+f"(c[mi][ni][3])
                        : "r"(a[mi][0]), "r"(a[mi][1]), "r"(a[mi][2]), "r"(a[mi][3]),
                          "r"(b0), "r"(b1));
                }
        }
        __syncthreads();
    }

    // epilogue
#pragma unroll
    for (int mi = 0; mi < 4; mi++) {
        const int row  = brow + wm * 64 + mi * 16 + (lane >> 2);
        const int row2 = row + 8;
        const float* ra = rowAdd ? rowAdd + (size_t)(row >> 4) * N : nullptr;
#pragma unroll
        for (int ni = 0; ni < 4; ni++) {
            const int col = bcol + wn * 32 + ni * 8 + (lane & 3) * 2;
            float v0 = c[mi][ni][0], v1 = c[mi][ni][1];
            float v2 = c[mi][ni][2], v3 = c[mi][ni][3];
            if (bias) {
                const float bb0 = bias[col], bb1 = bias[col + 1];
                v0 += bb0; v1 += bb1; v2 += bb0; v3 += bb1;
            }
            if (ra) {
                const float r0 = ra[col], r1 = ra[col + 1];
                v0 += r0; v1 += r1; v2 += r0; v3 += r1;
            }
            if (doRelu) {
                v0 = fmaxf(v0, 0.f); v1 = fmaxf(v1, 0.f);
                v2 = fmaxf(v2, 0.f); v3 = fmaxf(v3, 0.f);
            }
            if (Ch) {
                *(__half2*)&Ch[(size_t)row  * N + col] = __floats2half2_rn(v0, v1);
                *(__half2*)&Ch[(size_t)row2 * N + col] = __floats2half2_rn(v2, v3);
            } else {
                *(float2*)&Cf[(size_t)row  * N + col] = make_float2(v0, v1);
                *(float2*)&Cf[(size_t)row2 * N + col] = make_float2(v2, v3);
            }
        }
    }
}

// ---------------------------------------------------------------------------
// Weight packing fp32 -> fp16: Wcat=[W_pre|W_loc], then Wgcn, Wpost, W1, W2
// ---------------------------------------------------------------------------
__global__ void convW(const float* __restrict__ Wpre, const float* __restrict__ Wloc,
                      const float* __restrict__ Wgcn, const float* __restrict__ Wpost,
                      const float* __restrict__ W1, const float* __restrict__ W2,
                      __half* __restrict__ out)
{
    int idx = blockIdx.x * blockDim.x + threadIdx.x;
    if (idx >= WH_TOTAL) return;
    float v;
    if (idx < OFF_WGCN) {
        int k = idx / 384, j = idx % 384;
        v = (j < 128) ? Wpre[k * 128 + j] : Wloc[k * 256 + (j - 128)];
    }
    else if (idx < OFF_WPOST) v = Wgcn[idx - OFF_WGCN];
    else if (idx < OFF_W1)    v = Wpost[idx - OFF_WPOST];
    else if (idx < OFF_W2)    v = W1[idx - OFF_W1];
    else                      v = W2[idx - OFF_W2];
    out[idx] = __float2half_rn(v);
}

__global__ void fillBcat(const float* __restrict__ b_pre,
                         const float* __restrict__ b_loc, float* __restrict__ bcat)
{
    int i = threadIdx.x;
    bcat[i] = (i < 128) ? b_pre[i] : b_loc[i - 128];
}

// ---------------------------------------------------------------------------
// Mean over 16 agents, fp16 in (row stride s2 half2), fp16 out [S,128]
// ---------------------------------------------------------------------------
__global__ void mean16h(const __half2* __restrict__ x, __half2* __restrict__ xbar,
                        int S, int s2)
{
    int idx = blockIdx.x * blockDim.x + threadIdx.x;
    if (idx >= S * 64) return;
    int s = idx >> 6, cc = idx & 63;
    const __half2* p = x + (size_t)s * NAGENT * s2 + cc;
    float ax = 0.f, ay = 0.f;
#pragma unroll
    for (int a = 0; a < NAGENT; a++) {
        float2 v = __half22float2(p[(size_t)a * s2]);
        ax += v.x; ay += v.y;
    }
    xbar[(size_t)s * 64 + cc] = __floats2half2_rn(ax * (1.f / NAGENT), ay * (1.f / NAGENT));
}

// ---------------------------------------------------------------------------
// q[M,8] = z2[M,512](fp16) @ W3[512,8] + b3 (warp per row)
// ---------------------------------------------------------------------------
__global__ __launch_bounds__(256) void qgemm(
    const __half* __restrict__ z2, const float* __restrict__ W3,
    const float* __restrict__ b3, float* __restrict__ q, int M)
{
    __shared__ float W3s[F2 * NACT];
    for (int i = threadIdx.x; i < F2 * NACT; i += 256) W3s[i] = W3[i];
    __syncthreads();

    const int warp = threadIdx.x >> 5;
    const int lane = threadIdx.x & 31;
    const int row  = blockIdx.x * 8 + warp;
    if (row >= M) return;

    const __half2* zr = (const __half2*)(z2 + (size_t)row * F2);
    float acc[NACT] = {};
    for (int k2 = lane; k2 < F2 / 2; k2 += 32) {
        float2 z = __half22float2(zr[k2]);
        const float* w0 = &W3s[(2 * k2) * NACT];
#pragma unroll
        for (int n = 0; n < NACT; n++)
            acc[n] = fmaf(z.x, w0[n], fmaf(z.y, w0[NACT + n], acc[n]));
    }
#pragma unroll
    for (int n = 0; n < NACT; n++)
#pragma unroll
        for (int off = 16; off > 0; off >>= 1)
            acc[n] += __shfl_xor_sync(0xffffffff, acc[n], off);
    if (lane == 0) {
        float* qr = q + (size_t)row * NACT;
#pragma unroll
        for (int n = 0; n < NACT; n++) qr[n] = acc[n] + b3[n];
    }
}

// ---------------------------------------------------------------------------
extern "C" void kernel_launch(void* const* d_in, const int* in_sizes, int n_in,
                              void* d_out, int out_size)
{
    const float* obs    = (const float*)d_in[0];
    const float* W_pre  = (const float*)d_in[1];
    const float* b_pre  = (const float*)d_in[2];
    const float* W_gcn  = (const float*)d_in[3];
    const float* b_gcn  = (const float*)d_in[4];
    const float* W_post = (const float*)d_in[5];
    const float* b_post = (const float*)d_in[6];
    const float* W_loc  = (const float*)d_in[7];
    const float* b_loc  = (const float*)d_in[8];
    const float* W1     = (const float*)d_in[9];
    const float* b1     = (const float*)d_in[10];
    const float* W2     = (const float*)d_in[11];
    const float* b2     = (const float*)d_in[12];
    const float* W3     = (const float*)d_in[13];
    const float* b3     = (const float*)d_in[14];
    float* q = (float*)d_out;

    const int Bsz = in_sizes[0] / (NAGENT * OBS);   // 2048
    const int M   = Bsz * NAGENT;                   // 32768

    __half *wh, *xloc, *xbar, *s0, *s1, *gv, *z1, *z2;
    float *bcat, *G1;
    cudaGetSymbolAddress((void**)&wh,   g_wh);
    cudaGetSymbolAddress((void**)&bcat, g_bcat);
    cudaGetSymbolAddress((void**)&xloc, g_xloc);
    cudaGetSymbolAddress((void**)&xbar, g_xbar);
    cudaGetSymbolAddress((void**)&s0,   g_s0);
    cudaGetSymbolAddress((void**)&s1,   g_s1);
    cudaGetSymbolAddress((void**)&gv,   g_gv);
    cudaGetSymbolAddress((void**)&G1,   g_G1);
    cudaGetSymbolAddress((void**)&z1,   g_z1);
    cudaGetSymbolAddress((void**)&z2,   g_z2);

    convW<<<(WH_TOTAL + 255) / 256, 256>>>(W_pre, W_loc, W_gcn, W_post, W1, W2, wh);
    fillBcat<<<1, 384>>>(b_pre, b_loc, bcat);

    // 1) [x|loc] = relu(obs @ [W_pre|W_loc] + bcat)    [M,384], A fp32
    hgemm<1><<<dim3(384 / BN, M / BM), 256>>>(obs, wh + OFF_WCAT, xloc, nullptr,
                                              M, 384, OBS, OBS, bcat, nullptr, 1);
    // 2) xbar = mean over agents of x                  [B,128]
    mean16h<<<(Bsz * 64 + 255) / 256, 256>>>((const __half2*)xloc, (__half2*)xbar,
                                             Bsz, 192);
    // 3) collapsed GCN chain (per-sample rows)
    hgemm<0><<<dim3(1, Bsz / BM), 256>>>(xbar, wh + OFF_WGCN, s0, nullptr,
                                         Bsz, HID, HID, HID, b_gcn, nullptr, 1);
    hgemm<0><<<dim3(1, Bsz / BM), 256>>>(s0, wh + OFF_WGCN + HID * HID, s1, nullptr,
                                         Bsz, HID, HID, HID, b_gcn + HID, nullptr, 1);
    hgemm<0><<<dim3(GE / BN, Bsz / BM), 256>>>(s1, wh + OFF_WPOST, gv, nullptr,
                                               Bsz, GE, HID, HID, b_post, nullptr, 1);
    // 4) G1 = g @ W1[:256,:] + b1 (fp32 out)           [B,512]
    hgemm<0><<<dim3(F1 / BN, Bsz / BM), 256>>>(gv, wh + OFF_W1, nullptr, G1,
                                               Bsz, F1, GE, GE, b1, nullptr, 0);
    // 5) z1 = relu(loc @ W1[256:,:] + G1[sample])      [M,512]
    hgemm<0><<<dim3(F1 / BN, M / BM), 256>>>(xloc + 128, wh + OFF_W1 + GE * F1,
                                             z1, nullptr, M, F1, LE, 384,
                                             nullptr, G1, 1);
    // 6) z2 = relu(z1 @ W2 + b2)                       [M,512]
    hgemm<0><<<dim3(F2 / BN, M / BM), 256>>>(z1, wh + OFF_W2, z2, nullptr,
                                             M, F2, F1, F1, b2, nullptr, 1);
    // 7) q = z2 @ W3 + b3                              [M,8]
    qgemm<<<M / 8, 256>>>(z2, W3, b3, q, M);
}